// round 2
// baseline (speedup 1.0000x reference)
#include <cuda_runtime.h>
#include <cuda_fp16.h>
#include <cstdint>

#define Nn 100000
#define Mm 800000
#define FIN 64
#define FE  16
#define HH  64

// ---------------- device scratch (no allocations allowed) ----------------
__device__ __half  g_h2h[(size_t)Nn * 64];   // h2 rows in fp16 (128B/row)
__device__ float4  g_aggE[Nn * 12];          // aggregated edge_feat [N][3][16]
__device__ float   g_cntE[Nn * 3];           // per (dst, etype) counts
__device__ int     g_deg[Nn];
__device__ int     g_cur[Nn];
__device__ int     g_rs[Nn + 1];             // CSR row_start
__device__ int     g_tmp[100096];
__device__ int     g_bsum[392];
__device__ int     g_boff[392];
__device__ int     g_csrc[Mm];               // CSR payload: src node per edge
__device__ int     g_idx[2][Nn];             // per-type node lists
__device__ int     g_tcnt[2];

__device__ __forceinline__ void red_add_f4(float4* p, float4 v) {
    asm volatile("red.global.add.v4.f32 [%0], {%1,%2,%3,%4};"
                 :: "l"(p), "f"(v.x), "f"(v.y), "f"(v.z), "f"(v.w)
                 : "memory");
}

__device__ __forceinline__ uint32_t f2tf32(float f) {
    uint32_t u;
    asm("cvt.rna.tf32.f32 %0, %1;" : "=r"(u) : "f"(f));
    return u;
}

__device__ __forceinline__ void mma_tf32(float c[4], uint32_t a0, uint32_t a1,
                                         uint32_t a2, uint32_t a3,
                                         uint32_t b0, uint32_t b1) {
    asm volatile(
        "mma.sync.aligned.m16n8k8.row.col.f32.tf32.tf32.f32 "
        "{%0,%1,%2,%3},{%4,%5,%6,%7},{%8,%9},{%0,%1,%2,%3};"
        : "+f"(c[0]), "+f"(c[1]), "+f"(c[2]), "+f"(c[3])
        : "r"(a0), "r"(a1), "r"(a2), "r"(a3), "r"(b0), "r"(b1));
}

// ---------------- kernels ----------------

__global__ void zero_kernel() {
    int gid = blockIdx.x * blockDim.x + threadIdx.x;
    int stride = gridDim.x * blockDim.x;
    float4 z = make_float4(0.f, 0.f, 0.f, 0.f);
    for (int i = gid; i < Nn * 12; i += stride) g_aggE[i] = z;
    for (int i = gid; i < Nn * 3; i += stride) g_cntE[i] = 0.f;
    for (int i = gid; i < Nn; i += stride) { g_deg[i] = 0; g_cur[i] = 0; }
    if (gid < 2) g_tcnt[gid] = 0;
}

// 4 threads/edge: scatter-add ef into aggE[dst][etype]; fused dst histogram
__global__ void edge_scatter_kernel(const float* __restrict__ ef,
                                    const int* __restrict__ edst,
                                    const int* __restrict__ etype) {
    int gid = blockIdx.x * blockDim.x + threadIdx.x;
    int e = gid >> 2, q = gid & 3;
    if (e >= Mm) return;
    int dst = edst[e];
    int t   = etype[e];
    float4 v = ((const float4*)ef)[e * 4 + q];
    red_add_f4(&g_aggE[dst * 12 + t * 4 + q], v);
    if (q == 0) {
        atomicAdd(&g_cntE[dst * 3 + t], 1.0f);
        atomicAdd(&g_deg[dst], 1);
    }
}

// ---- 3-phase exclusive scan of g_deg -> g_rs ----
__global__ void scan_a_kernel() {
    const unsigned FULL = 0xffffffffu;
    int b = blockIdx.x, t = threadIdx.x;
    int i = b * 256 + t;
    int v = (i < Nn) ? g_deg[i] : 0;
    int lane = t & 31, w = t >> 5;
    int s = v;
    #pragma unroll
    for (int o = 1; o < 32; o <<= 1) {
        int n = __shfl_up_sync(FULL, s, o);
        if (lane >= o) s += n;
    }
    __shared__ int wt[8];
    if (lane == 31) wt[w] = s;
    __syncthreads();
    if (w == 0) {
        int x = (lane < 8) ? wt[lane] : 0;
        #pragma unroll
        for (int o = 1; o < 8; o <<= 1) {
            int n = __shfl_up_sync(FULL, x, o);
            if (lane >= o) x += n;
        }
        if (lane < 8) wt[lane] = x;
    }
    __syncthreads();
    int incl = s + (w > 0 ? wt[w - 1] : 0);
    g_tmp[i] = incl;
    if (t == 255) g_bsum[b] = incl;
}

__global__ void scan_b_kernel(int nb) {
    __shared__ int s[512];
    int t = threadIdx.x;
    int v = (t < nb) ? g_bsum[t] : 0;
    s[t] = v;
    __syncthreads();
    for (int o = 1; o < 512; o <<= 1) {
        int n = (t >= o) ? s[t - o] : 0;
        __syncthreads();
        s[t] += n;
        __syncthreads();
    }
    if (t < nb) g_boff[t] = s[t] - v;   // exclusive
}

__global__ void scan_c_kernel() {
    int i = blockIdx.x * blockDim.x + threadIdx.x;
    if (i < Nn) {
        g_rs[i + 1] = g_tmp[i] + g_boff[i >> 8];
        if (i == 0) g_rs[0] = 0;
    }
}

__global__ void csr_fill_kernel(const int* __restrict__ esrc,
                                const int* __restrict__ edst) {
    int e = blockIdx.x * blockDim.x + threadIdx.x;
    if (e >= Mm) return;
    int d = edst[e];
    int p = g_rs[d] + atomicAdd(&g_cur[d], 1);
    g_csrc[p] = esrc[e];
}

__global__ void partition_kernel(const int* __restrict__ ntype) {
    int i = blockIdx.x * blockDim.x + threadIdx.x;
    if (i >= Nn) return;
    int t = ntype[i];
    int p = atomicAdd(&g_tcnt[t], 1);
    g_idx[t][p] = i;
}

// Node GEMM (tf32 tensor cores), type-partitioned tiles of 64 nodes.
// A[64 x 120] = [x(64) | aggE(48) | cnt(3) | 0(5)]
// B[120 x 128] = [[W1|W2],[W5|0],[b5|0],[0|0]]  (for the tile's node type)
// Output cols 0..63  -> out   (h1 + agg + b1)
//        cols 64..127-> g_h2h (h2 + b2, fp16)
#define XS_STRIDE 124
#define WS_STRIDE 132
__global__ __launch_bounds__(256, 2)
void node_gemm_kernel(const float* __restrict__ x,
                      const float* __restrict__ W1, const float* __restrict__ b1,
                      const float* __restrict__ W2, const float* __restrict__ b2,
                      const float* __restrict__ W5, const float* __restrict__ b5,
                      float* __restrict__ out) {
    extern __shared__ float sm[];
    float* Ws = sm;                        // [120][132]
    float* xs = sm + 120 * WS_STRIDE;      // [64][124]
    float* bc = xs + 64 * XS_STRIDE;       // [128]
    int* sidx = (int*)(bc + 128);          // [64]

    int tid = threadIdx.x;
    int c0n = g_tcnt[0];
    int tiles0 = (c0n + 63) >> 6;
    int c1n = Nn - c0n;
    int tiles1 = (c1n + 63) >> 6;

    const int* list;
    int base, cnt, typ;
    int b = blockIdx.x;
    if (b < tiles0) { list = g_idx[0]; base = b * 64; cnt = c0n; typ = 0; }
    else {
        int b2i = b - tiles0;
        if (b2i >= tiles1) return;
        list = g_idx[1]; base = b2i * 64; cnt = c1n; typ = 1;
    }

    // B tile (tf32-rounded) + biases
    const float* W1t = W1 + typ * (FIN * HH);
    const float* W2t = W2 + typ * (FIN * HH);
    for (int i = tid; i < 120 * 128; i += 256) {
        int kk = i >> 7, c = i & 127;
        float v = 0.f;
        if (kk < 64) v = (c < 64) ? W1t[kk * 64 + c] : W2t[kk * 64 + (c - 64)];
        else if (kk < 112) { if (c < 64) v = W5[(kk - 64) * 64 + c]; }
        else if (kk < 115) { if (c < 64) v = b5[(kk - 112) * 64 + c]; }
        Ws[kk * WS_STRIDE + c] = __uint_as_float(f2tf32(v));
    }
    if (tid < 128)
        bc[tid] = (tid < 64) ? b1[typ * 64 + tid] : b2[typ * 64 + (tid - 64)];
    if (tid < 64) {
        int j = base + tid;
        sidx[tid] = (j < cnt) ? list[j] : -1;
    }
    __syncthreads();

    // gather A rows (x, aggE, cnt), tf32-rounded
    {
        int r = tid >> 2, sub = tid & 3;
        int node = sidx[r];
        float* row = xs + r * XS_STRIDE;
        if (node >= 0) {
            const float4* x4 = (const float4*)x;
            for (int ii = sub; ii < 16; ii += 4) {
                float4 v = x4[node * 16 + ii];
                float4 o;
                o.x = __uint_as_float(f2tf32(v.x)); o.y = __uint_as_float(f2tf32(v.y));
                o.z = __uint_as_float(f2tf32(v.z)); o.w = __uint_as_float(f2tf32(v.w));
                *(float4*)(row + ii * 4) = o;
            }
            for (int ii = sub; ii < 12; ii += 4) {
                float4 v = g_aggE[node * 12 + ii];
                float4 o;
                o.x = __uint_as_float(f2tf32(v.x)); o.y = __uint_as_float(f2tf32(v.y));
                o.z = __uint_as_float(f2tf32(v.z)); o.w = __uint_as_float(f2tf32(v.w));
                *(float4*)(row + 64 + ii * 4) = o;
            }
            if (sub == 0) {
                #pragma unroll
                for (int t3 = 0; t3 < 3; t3++)
                    row[112 + t3] = __uint_as_float(f2tf32(g_cntE[node * 3 + t3]));
                #pragma unroll
                for (int p = 115; p < 120; p++) row[p] = 0.f;
            }
        } else {
            float4 z = make_float4(0.f, 0.f, 0.f, 0.f);
            for (int ii = sub; ii < 30; ii += 4) *(float4*)(row + ii * 4) = z;
        }
    }
    __syncthreads();

    // MMA: warp w -> rows 16*(w&3), cols 64*(w>>2)
    int w = tid >> 5, lane = tid & 31;
    int g = lane >> 2, tq = lane & 3;
    int rbase = (w & 3) * 16, cbase = (w >> 2) * 64;

    float acc[8][4];
    #pragma unroll
    for (int nt = 0; nt < 8; nt++)
        #pragma unroll
        for (int j = 0; j < 4; j++) acc[nt][j] = 0.f;

    #pragma unroll
    for (int kk = 0; kk < 120; kk += 8) {
        uint32_t a0 = __float_as_uint(xs[(rbase + g) * XS_STRIDE + kk + tq]);
        uint32_t a1 = __float_as_uint(xs[(rbase + g + 8) * XS_STRIDE + kk + tq]);
        uint32_t a2 = __float_as_uint(xs[(rbase + g) * XS_STRIDE + kk + tq + 4]);
        uint32_t a3 = __float_as_uint(xs[(rbase + g + 8) * XS_STRIDE + kk + tq + 4]);
        #pragma unroll
        for (int nt = 0; nt < 8; nt++) {
            int col0 = cbase + nt * 8;
            uint32_t b0 = __float_as_uint(Ws[(kk + tq) * WS_STRIDE + col0 + g]);
            uint32_t b1r = __float_as_uint(Ws[(kk + tq + 4) * WS_STRIDE + col0 + g]);
            mma_tf32(acc[nt], a0, a1, a2, a3, b0, b1r);
        }
    }

    // write out: rows g and g+8, col pairs
    __half2* h2p = (__half2*)g_h2h;
    float2* outp = (float2*)out;
    #pragma unroll
    for (int nt = 0; nt < 8; nt++) {
        int col0 = cbase + nt * 8 + 2 * tq;
        float bcv0 = bc[col0], bcv1 = bc[col0 + 1];
        #pragma unroll
        for (int half_r = 0; half_r < 2; half_r++) {
            int r = rbase + g + half_r * 8;
            int node = sidx[r];
            if (node < 0) continue;
            float v0 = acc[nt][half_r * 2 + 0] + bcv0;
            float v1 = acc[nt][half_r * 2 + 1] + bcv1;
            if (col0 < 64) {
                outp[node * 32 + (col0 >> 1)] = make_float2(v0, v1);
            } else {
                h2p[node * 32 + ((col0 - 64) >> 1)] = __floats2half2_rn(v0, v1);
            }
        }
    }
}

// CSR gather: out[dst] += sum over incident edges of h2[src] (fp16 rows)
__global__ __launch_bounds__(256)
void h2_gather_kernel(float* __restrict__ out) {
    int tid = threadIdx.x;
    int node = blockIdx.x * 16 + (tid >> 4);
    int q = tid & 15;
    if (node >= Nn) return;
    int r0 = g_rs[node], r1 = g_rs[node + 1];
    if (r0 == r1) return;

    const uint2* H = (const uint2*)g_h2h;
    float4 acc = make_float4(0.f, 0.f, 0.f, 0.f);

    auto add4 = [&](uint2 hv) {
        __half2 p0 = *(__half2*)&hv.x, p1 = *(__half2*)&hv.y;
        float2 f0 = __half22float2(p0), f1 = __half22float2(p1);
        acc.x += f0.x; acc.y += f0.y; acc.z += f1.x; acc.w += f1.y;
    };

    int i = r0;
    for (; i + 4 <= r1; i += 4) {
        int s0 = __ldg(&g_csrc[i]);
        int s1 = __ldg(&g_csrc[i + 1]);
        int s2 = __ldg(&g_csrc[i + 2]);
        int s3 = __ldg(&g_csrc[i + 3]);
        uint2 v0 = __ldg(&H[s0 * 16 + q]);
        uint2 v1 = __ldg(&H[s1 * 16 + q]);
        uint2 v2 = __ldg(&H[s2 * 16 + q]);
        uint2 v3 = __ldg(&H[s3 * 16 + q]);
        add4(v0); add4(v1); add4(v2); add4(v3);
    }
    for (; i < r1; i++) {
        int s0 = __ldg(&g_csrc[i]);
        add4(__ldg(&H[s0 * 16 + q]));
    }

    float4* o4 = (float4*)out;
    float4 o = o4[node * 16 + q];
    o.x += acc.x; o.y += acc.y; o.z += acc.z; o.w += acc.w;
    o4[node * 16 + q] = o;
}

// ---------------- launch ----------------
extern "C" void kernel_launch(void* const* d_in, const int* in_sizes, int n_in,
                              void* d_out, int out_size) {
    const float *x = nullptr, *ef = nullptr;
    const float *W[4] = {nullptr, nullptr, nullptr, nullptr};
    const float *B[4] = {nullptr, nullptr, nullptr, nullptr};
    const float *W5 = nullptr, *b5 = nullptr;
    const int *ntype = nullptr, *esrc = nullptr, *edst = nullptr, *etype = nullptr;
    int wI = 0, bI = 0, mI = 0;
    for (int i = 0; i < n_in; i++) {
        long s = in_sizes[i];
        const void* p = d_in[i];
        if (s == (long)Nn * FIN)      x = (const float*)p;
        else if (s == (long)Mm * FE)  ef = (const float*)p;
        else if (s == Nn)             ntype = (const int*)p;
        else if (s == Mm) {
            if (mI == 0) esrc = (const int*)p;
            else if (mI == 1) edst = (const int*)p;
            else etype = (const int*)p;
            mI++;
        }
        else if (s == 2 * FIN * HH) { if (wI < 4) W[wI++] = (const float*)p; }
        else if (s == 2 * HH)       { if (bI < 4) B[bI++] = (const float*)p; }
        else if (s == 3 * FE * HH)  W5 = (const float*)p;
        else if (s == 3 * HH)       b5 = (const float*)p;
    }
    float* out = (float*)d_out;

    const int smem_bytes = (120 * WS_STRIDE + 64 * XS_STRIDE + 128) * 4 + 64 * 4;
    cudaFuncSetAttribute(node_gemm_kernel,
                         cudaFuncAttributeMaxDynamicSharedMemorySize, 100 * 1024);

    zero_kernel<<<2048, 256>>>();
    edge_scatter_kernel<<<(Mm * 4 + 255) / 256, 256>>>(ef, edst, etype);
    scan_a_kernel<<<391, 256>>>();
    scan_b_kernel<<<1, 512>>>(391);
    scan_c_kernel<<<(Nn + 255) / 256, 256>>>();
    csr_fill_kernel<<<(Mm + 255) / 256, 256>>>(esrc, edst);
    partition_kernel<<<(Nn + 255) / 256, 256>>>(ntype);
    node_gemm_kernel<<<(Nn + 63) / 64 + 1, 256, smem_bytes>>>(
        x, W[0], B[0], W[1], B[1], W5, b5, out);
    h2_gather_kernel<<<(Nn + 15) / 16, 256>>>(out);
}

// round 3
// speedup vs baseline: 1.5602x; 1.5602x over previous
#include <cuda_runtime.h>
#include <cuda_fp16.h>
#include <cstdint>

#define Nn 100000
#define Mm 800000
#define FIN 64
#define FE  16
#define HH  64

// ---------------- device scratch (no allocations allowed) ----------------
__device__ __half  g_h2h[(size_t)Nn * 64];   // h2 rows in fp16 (128B/row)
__device__ float4  g_aggE[Nn * 12];          // aggregated edge_feat [N][3][16]
__device__ float   g_cntE[Nn * 3];           // per (dst, etype) counts
__device__ int     g_idx[2][Nn];             // per-type node lists
__device__ int     g_tcnt[2];

__device__ __forceinline__ void red_add_f4(float4* p, float4 v) {
    asm volatile("red.global.add.v4.f32 [%0], {%1,%2,%3,%4};"
                 :: "l"(p), "f"(v.x), "f"(v.y), "f"(v.z), "f"(v.w)
                 : "memory");
}

__device__ __forceinline__ uint32_t f2tf32(float f) {
    uint32_t u;
    asm("cvt.rna.tf32.f32 %0, %1;" : "=r"(u) : "f"(f));
    return u;
}

__device__ __forceinline__ void mma_tf32(float c[4], uint32_t a0, uint32_t a1,
                                         uint32_t a2, uint32_t a3,
                                         uint32_t b0, uint32_t b1) {
    asm volatile(
        "mma.sync.aligned.m16n8k8.row.col.f32.tf32.tf32.f32 "
        "{%0,%1,%2,%3},{%4,%5,%6,%7},{%8,%9},{%0,%1,%2,%3};"
        : "+f"(c[0]), "+f"(c[1]), "+f"(c[2]), "+f"(c[3])
        : "r"(a0), "r"(a1), "r"(a2), "r"(a3), "r"(b0), "r"(b1));
}

// ---------------- kernels ----------------

__global__ void zero_kernel() {
    int gid = blockIdx.x * blockDim.x + threadIdx.x;
    int stride = gridDim.x * blockDim.x;
    float4 z = make_float4(0.f, 0.f, 0.f, 0.f);
    for (int i = gid; i < Nn * 12; i += stride) g_aggE[i] = z;
    for (int i = gid; i < Nn * 3; i += stride) g_cntE[i] = 0.f;
    if (gid < 2) g_tcnt[gid] = 0;
}

// 4 threads/edge: scatter-add ef into aggE[dst][etype] + count
__global__ void edge_scatter_kernel(const float* __restrict__ ef,
                                    const int* __restrict__ edst,
                                    const int* __restrict__ etype) {
    int gid = blockIdx.x * blockDim.x + threadIdx.x;
    int e = gid >> 2, q = gid & 3;
    if (e >= Mm) return;
    int dst = edst[e];
    int t   = etype[e];
    float4 v = ((const float4*)ef)[e * 4 + q];
    red_add_f4(&g_aggE[dst * 12 + t * 4 + q], v);
    if (q == 0) atomicAdd(&g_cntE[dst * 3 + t], 1.0f);
}

// warp-aggregated partition by node type (2 atomics per warp)
__global__ void partition_kernel(const int* __restrict__ ntype) {
    const unsigned FULL = 0xffffffffu;
    int i = blockIdx.x * blockDim.x + threadIdx.x;
    int lane = threadIdx.x & 31;
    bool valid = (i < Nn);
    int t = valid ? ntype[i] : -1;
    unsigned m0 = __ballot_sync(FULL, t == 0);
    unsigned m1 = __ballot_sync(FULL, t == 1);
    int base0 = 0, base1 = 0;
    if (lane == 0) {
        if (m0) base0 = atomicAdd(&g_tcnt[0], __popc(m0));
        if (m1) base1 = atomicAdd(&g_tcnt[1], __popc(m1));
    }
    base0 = __shfl_sync(FULL, base0, 0);
    base1 = __shfl_sync(FULL, base1, 0);
    unsigned lt = (1u << lane) - 1u;
    if (t == 0) g_idx[0][base0 + __popc(m0 & lt)] = i;
    else if (t == 1) g_idx[1][base1 + __popc(m1 & lt)] = i;
}

// Persistent node GEMM (tf32 tensor cores), type-partitioned tiles of 64 nodes.
// A[64 x 120] = [x(64) | aggE(48) | cnt(3) | 0(5)]
// B[120 x 128] = [[W1|W2],[W5|0],[b5|0],[0|0]]  (for tile's node type)
// cols 0..63  -> out (h1 + agg + b1); cols 64..127 -> g_h2h (h2 + b2, fp16)
#define XS_STRIDE 124
#define WS_STRIDE 136
__global__ __launch_bounds__(256, 2)
void node_gemm_kernel(const float* __restrict__ x,
                      const float* __restrict__ W1, const float* __restrict__ b1,
                      const float* __restrict__ W2, const float* __restrict__ b2,
                      const float* __restrict__ W5, const float* __restrict__ b5,
                      float* __restrict__ out) {
    extern __shared__ float sm[];
    float* Ws = sm;                        // [120][136]
    float* xs = sm + 120 * WS_STRIDE;      // [64][124]
    float* bc = xs + 64 * XS_STRIDE;       // [128]
    int* sidx = (int*)(bc + 128);          // [64]

    int tid = threadIdx.x;
    int w = tid >> 5, lane = tid & 31;
    int g = lane >> 2, tq = lane & 3;
    int rbase = (w & 3) * 16, cbase = (w >> 2) * 64;

    int c0n = g_tcnt[0];
    int tiles0 = (c0n + 63) >> 6;
    int c1n = Nn - c0n;
    int tiles1 = (c1n + 63) >> 6;
    int total = tiles0 + tiles1;

    int tpb = (total + gridDim.x - 1) / gridDim.x;
    int t_begin = blockIdx.x * tpb;
    int t_end = min(t_begin + tpb, total);

    int cur_typ = -1;
    for (int tile = t_begin; tile < t_end; tile++) {
        int typ, base, cnt;
        const int* list;
        if (tile < tiles0) { typ = 0; list = g_idx[0]; base = (tile) * 64; cnt = c0n; }
        else { typ = 1; list = g_idx[1]; base = (tile - tiles0) * 64; cnt = c1n; }

        __syncthreads();   // previous iteration's smem readers done

        if (typ != cur_typ) {
            cur_typ = typ;
            const float* W1t = W1 + typ * (FIN * HH);
            const float* W2t = W2 + typ * (FIN * HH);
            for (int i = tid; i < 120 * 128; i += 256) {
                int kk = i >> 7, c = i & 127;
                float v = 0.f;
                if (kk < 64) v = (c < 64) ? W1t[kk * 64 + c] : W2t[kk * 64 + (c - 64)];
                else if (kk < 112) { if (c < 64) v = W5[(kk - 64) * 64 + c]; }
                else if (kk < 115) { if (c < 64) v = b5[(kk - 112) * 64 + c]; }
                Ws[kk * WS_STRIDE + c] = __uint_as_float(f2tf32(v));
            }
            if (tid < 128)
                bc[tid] = (tid < 64) ? b1[typ * 64 + tid] : b2[typ * 64 + (tid - 64)];
        }
        if (tid < 64) {
            int j = base + tid;
            sidx[tid] = (j < cnt) ? list[j] : -1;
        }
        __syncthreads();

        // gather A rows (x, aggE, cnt), tf32-rounded; 4 threads per row
        {
            int r = tid >> 2, sub = tid & 3;
            int node = sidx[r];
            float* row = xs + r * XS_STRIDE;
            if (node >= 0) {
                const float4* x4 = (const float4*)x;
                for (int ii = sub; ii < 16; ii += 4) {
                    float4 v = x4[node * 16 + ii];
                    float4 o;
                    o.x = __uint_as_float(f2tf32(v.x)); o.y = __uint_as_float(f2tf32(v.y));
                    o.z = __uint_as_float(f2tf32(v.z)); o.w = __uint_as_float(f2tf32(v.w));
                    *(float4*)(row + ii * 4) = o;
                }
                for (int ii = sub; ii < 12; ii += 4) {
                    float4 v = g_aggE[node * 12 + ii];
                    float4 o;
                    o.x = __uint_as_float(f2tf32(v.x)); o.y = __uint_as_float(f2tf32(v.y));
                    o.z = __uint_as_float(f2tf32(v.z)); o.w = __uint_as_float(f2tf32(v.w));
                    *(float4*)(row + 64 + ii * 4) = o;
                }
                if (sub == 0) {
                    #pragma unroll
                    for (int t3 = 0; t3 < 3; t3++)
                        row[112 + t3] = __uint_as_float(f2tf32(g_cntE[node * 3 + t3]));
                    #pragma unroll
                    for (int p = 115; p < 120; p++) row[p] = 0.f;
                }
            } else {
                float4 z = make_float4(0.f, 0.f, 0.f, 0.f);
                for (int ii = sub; ii < 30; ii += 4) *(float4*)(row + ii * 4) = z;
            }
        }
        __syncthreads();

        float acc[8][4];
        #pragma unroll
        for (int nt = 0; nt < 8; nt++)
            #pragma unroll
            for (int j = 0; j < 4; j++) acc[nt][j] = 0.f;

        #pragma unroll
        for (int kk = 0; kk < 120; kk += 8) {
            uint32_t a0 = __float_as_uint(xs[(rbase + g) * XS_STRIDE + kk + tq]);
            uint32_t a1 = __float_as_uint(xs[(rbase + g + 8) * XS_STRIDE + kk + tq]);
            uint32_t a2 = __float_as_uint(xs[(rbase + g) * XS_STRIDE + kk + tq + 4]);
            uint32_t a3 = __float_as_uint(xs[(rbase + g + 8) * XS_STRIDE + kk + tq + 4]);
            #pragma unroll
            for (int nt = 0; nt < 8; nt++) {
                int col0 = cbase + nt * 8;
                uint32_t b0 = __float_as_uint(Ws[(kk + tq) * WS_STRIDE + col0 + g]);
                uint32_t b1r = __float_as_uint(Ws[(kk + tq + 4) * WS_STRIDE + col0 + g]);
                mma_tf32(acc[nt], a0, a1, a2, a3, b0, b1r);
            }
        }

        __half2* h2p = (__half2*)g_h2h;
        float2* outp = (float2*)out;
        #pragma unroll
        for (int nt = 0; nt < 8; nt++) {
            int col0 = cbase + nt * 8 + 2 * tq;
            float bcv0 = bc[col0], bcv1 = bc[col0 + 1];
            #pragma unroll
            for (int half_r = 0; half_r < 2; half_r++) {
                int r = rbase + g + half_r * 8;
                int node = sidx[r];
                if (node < 0) continue;
                float v0 = acc[nt][half_r * 2 + 0] + bcv0;
                float v1 = acc[nt][half_r * 2 + 1] + bcv1;
                if (col0 < 64) {
                    outp[node * 32 + (col0 >> 1)] = make_float2(v0, v1);
                } else {
                    h2p[node * 32 + ((col0 - 64) >> 1)] = __floats2half2_rn(v0, v1);
                }
            }
        }
    }
}

// 8 threads/edge: out[dst] += h2[src] (fp16 gather, fp32 red.v4 scatter)
__global__ void h2_scatter_kernel(const int* __restrict__ esrc,
                                  const int* __restrict__ edst,
                                  float4* __restrict__ out) {
    int gid = blockIdx.x * blockDim.x + threadIdx.x;
    int e = gid >> 3, q = gid & 7;
    if (e >= Mm) return;
    int src = esrc[e];
    int dst = edst[e];
    uint4 hv = ((const uint4*)g_h2h)[src * 8 + q];   // 8 halfs
    float2 f0 = __half22float2(*(__half2*)&hv.x);
    float2 f1 = __half22float2(*(__half2*)&hv.y);
    float2 f2 = __half22float2(*(__half2*)&hv.z);
    float2 f3 = __half22float2(*(__half2*)&hv.w);
    red_add_f4(&out[dst * 16 + q * 2],     make_float4(f0.x, f0.y, f1.x, f1.y));
    red_add_f4(&out[dst * 16 + q * 2 + 1], make_float4(f2.x, f2.y, f3.x, f3.y));
}

// ---------------- launch ----------------
extern "C" void kernel_launch(void* const* d_in, const int* in_sizes, int n_in,
                              void* d_out, int out_size) {
    const float *x = nullptr, *ef = nullptr;
    const float *W[4] = {nullptr, nullptr, nullptr, nullptr};
    const float *B[4] = {nullptr, nullptr, nullptr, nullptr};
    const float *W5 = nullptr, *b5 = nullptr;
    const int *ntype = nullptr, *esrc = nullptr, *edst = nullptr, *etype = nullptr;
    int wI = 0, bI = 0, mI = 0;
    for (int i = 0; i < n_in; i++) {
        long s = in_sizes[i];
        const void* p = d_in[i];
        if (s == (long)Nn * FIN)      x = (const float*)p;
        else if (s == (long)Mm * FE)  ef = (const float*)p;
        else if (s == Nn)             ntype = (const int*)p;
        else if (s == Mm) {
            if (mI == 0) esrc = (const int*)p;
            else if (mI == 1) edst = (const int*)p;
            else etype = (const int*)p;
            mI++;
        }
        else if (s == 2 * FIN * HH) { if (wI < 4) W[wI++] = (const float*)p; }
        else if (s == 2 * HH)       { if (bI < 4) B[bI++] = (const float*)p; }
        else if (s == 3 * FE * HH)  W5 = (const float*)p;
        else if (s == 3 * HH)       b5 = (const float*)p;
    }
    float* out = (float*)d_out;

    const int smem_bytes = (120 * WS_STRIDE + 64 * XS_STRIDE + 128) * 4 + 64 * 4;
    cudaFuncSetAttribute(node_gemm_kernel,
                         cudaFuncAttributeMaxDynamicSharedMemorySize, 110 * 1024);

    zero_kernel<<<2048, 256>>>();
    edge_scatter_kernel<<<(Mm * 4 + 255) / 256, 256>>>(ef, edst, etype);
    partition_kernel<<<(Nn + 255) / 256, 256>>>(ntype);
    node_gemm_kernel<<<296, 256, smem_bytes>>>(
        x, W[0], B[0], W[1], B[1], W5, b5, out);
    h2_scatter_kernel<<<(Mm * 8 + 255) / 256, 256>>>(esrc, edst, (float4*)out);
}

// round 4
// speedup vs baseline: 2.0767x; 1.3311x over previous
#include <cuda_runtime.h>
#include <cuda_fp16.h>
#include <cstdint>

#define Nn 100000
#define Mm 800000
#define FIN 64
#define FE  16
#define HH  64
#define CAP 48

// ---------------- device scratch (no allocations allowed) ----------------
__device__ __half  g_h2h[(size_t)Nn * 64];    // h2 rows fp16 (128B/row)
__device__ float4  g_aggE[Nn * 12];           // aggregated edge_feat [N][3][16]
__device__ float   g_cntE[Nn * 3];            // per (dst, etype) counts
__device__ int     g_cur[Nn];                 // bucket cursors
__device__ int     g_slots[(size_t)Nn * CAP]; // bucket payload: src per incident edge
__device__ int     g_idx[2][Nn];              // per-type node lists
__device__ int     g_tcnt[2];
__device__ int     g_ovf_cnt;
__device__ int2    g_ovf[8192];               // overflow edges (src,dst)

__device__ __forceinline__ void red_add_f4(float4* p, float4 v) {
    asm volatile("red.global.add.v4.f32 [%0], {%1,%2,%3,%4};"
                 :: "l"(p), "f"(v.x), "f"(v.y), "f"(v.z), "f"(v.w)
                 : "memory");
}

__device__ __forceinline__ uint32_t f2tf32(float f) {
    uint32_t u;
    asm("cvt.rna.tf32.f32 %0, %1;" : "=r"(u) : "f"(f));
    return u;
}
__device__ __forceinline__ float tf32f(float f) { return __uint_as_float(f2tf32(f)); }

__device__ __forceinline__ void mma_tf32(float c[4], uint32_t a0, uint32_t a1,
                                         uint32_t a2, uint32_t a3,
                                         uint32_t b0, uint32_t b1) {
    asm volatile(
        "mma.sync.aligned.m16n8k8.row.col.f32.tf32.tf32.f32 "
        "{%0,%1,%2,%3},{%4,%5,%6,%7},{%8,%9},{%0,%1,%2,%3};"
        : "+f"(c[0]), "+f"(c[1]), "+f"(c[2]), "+f"(c[3])
        : "r"(a0), "r"(a1), "r"(a2), "r"(a3), "r"(b0), "r"(b1));
}

// ---------------- kernels ----------------

__global__ void zero_kernel() {
    int gid = blockIdx.x * blockDim.x + threadIdx.x;
    int stride = gridDim.x * blockDim.x;
    float4 z = make_float4(0.f, 0.f, 0.f, 0.f);
    for (int i = gid; i < Nn * 12; i += stride) g_aggE[i] = z;
    for (int i = gid; i < Nn * 3; i += stride) g_cntE[i] = 0.f;
    for (int i = gid; i < Nn; i += stride) g_cur[i] = 0;
    if (gid < 2) g_tcnt[gid] = 0;
    if (gid == 2) g_ovf_cnt = 0;
}

// 4 threads/edge: scatter-add ef into aggE[dst][etype]; fused count + bucket fill
__global__ void edge_scatter_kernel(const float* __restrict__ ef,
                                    const int* __restrict__ esrc,
                                    const int* __restrict__ edst,
                                    const int* __restrict__ etype) {
    int gid = blockIdx.x * blockDim.x + threadIdx.x;
    int e = gid >> 2, q = gid & 3;
    if (e >= Mm) return;
    int dst = edst[e];
    int t   = etype[e];
    float4 v = ((const float4*)ef)[e * 4 + q];
    red_add_f4(&g_aggE[dst * 12 + t * 4 + q], v);
    if (q == 0) {
        atomicAdd(&g_cntE[dst * 3 + t], 1.0f);
        int src = esrc[e];
        int p = atomicAdd(&g_cur[dst], 1);
        if (p < CAP) {
            g_slots[(size_t)dst * CAP + p] = src;
        } else {
            int o = atomicAdd(&g_ovf_cnt, 1);
            if (o < 8192) g_ovf[o] = make_int2(src, dst);
        }
    }
}

// warp-aggregated partition by node type (2 atomics per warp)
__global__ void partition_kernel(const int* __restrict__ ntype) {
    const unsigned FULL = 0xffffffffu;
    int i = blockIdx.x * blockDim.x + threadIdx.x;
    int lane = threadIdx.x & 31;
    bool valid = (i < Nn);
    int t = valid ? ntype[i] : -1;
    unsigned m0 = __ballot_sync(FULL, t == 0);
    unsigned m1 = __ballot_sync(FULL, t == 1);
    int base0 = 0, base1 = 0;
    if (lane == 0) {
        if (m0) base0 = atomicAdd(&g_tcnt[0], __popc(m0));
        if (m1) base1 = atomicAdd(&g_tcnt[1], __popc(m1));
    }
    base0 = __shfl_sync(FULL, base0, 0);
    base1 = __shfl_sync(FULL, base1, 0);
    unsigned lt = (1u << lane) - 1u;
    if (t == 0) g_idx[0][base0 + __popc(m0 & lt)] = i;
    else if (t == 1) g_idx[1][base1 + __popc(m1 & lt)] = i;
}

// Persistent node GEMM (tf32 mma), 512 threads, tile M=128, register-pipelined
// A[128 x 120] = [x(64) | aggE(48) | cnt(3) | 0(5)]
// B[120 x 128] = [[W1|W2],[W5|0],[b5|0],[0|0]] (per type)
// cols 0..63 -> out (fp32); cols 64..127 -> g_h2h (fp16)
#define XS_STRIDE 124
#define WS_STRIDE 136
__global__ __launch_bounds__(512, 1)
void node_gemm_kernel(const float* __restrict__ x,
                      const float* __restrict__ W1, const float* __restrict__ b1,
                      const float* __restrict__ W2, const float* __restrict__ b2,
                      const float* __restrict__ W5, const float* __restrict__ b5,
                      float* __restrict__ out) {
    extern __shared__ float sm[];
    float* Ws = sm;                         // [120][136]
    float* xs = Ws + 120 * WS_STRIDE;       // [128][124]
    float* bc = xs + 128 * XS_STRIDE;       // [128]
    int* sidx = (int*)(bc + 128);           // [128]

    const int tid = threadIdx.x;
    const int w = tid >> 5, lane = tid & 31;
    const int g = lane >> 2, tq = lane & 3;
    const int rbase = (w & 7) * 16, cbase = (w >> 3) * 64;
    const int r = tid >> 2, sub = tid & 3;

    const int c0n = g_tcnt[0];
    const int tiles0 = (c0n + 127) >> 7;
    const int c1n = Nn - c0n;
    const int tiles1 = (c1n + 127) >> 7;
    const int total = tiles0 + tiles1;
    const int tpb = (total + gridDim.x - 1) / gridDim.x;
    const int t_begin = blockIdx.x * tpb;
    const int t_end = min(t_begin + tpb, total);
    if (t_begin >= t_end) return;

    // register staging for the A tile (loaded for tile t+1 while t computes)
    float4 rx[4], ra[3];
    float rc = 0.f;
    int snode = -1;

    auto stage_load = [&](int tile) {
        int typ = (tile < tiles0) ? 0 : 1;
        const int* list = g_idx[typ];
        int base = ((typ == 0) ? tile : (tile - tiles0)) << 7;
        int cnt = (typ == 0) ? c0n : c1n;
        int j = base + r;
        snode = (j < cnt) ? list[j] : -1;
        if (snode >= 0) {
            const float4* x4 = (const float4*)x;
            #pragma unroll
            for (int ii = 0; ii < 4; ii++) rx[ii] = x4[snode * 16 + sub + 4 * ii];
            #pragma unroll
            for (int ii = 0; ii < 3; ii++) ra[ii] = g_aggE[snode * 12 + sub + 4 * ii];
            rc = (sub < 3) ? g_cntE[snode * 3 + sub] : 0.f;
        } else {
            float4 z = make_float4(0.f, 0.f, 0.f, 0.f);
            #pragma unroll
            for (int ii = 0; ii < 4; ii++) rx[ii] = z;
            #pragma unroll
            for (int ii = 0; ii < 3; ii++) ra[ii] = z;
            rc = 0.f;
        }
    };

    auto stage_store = [&]() {
        float* row = xs + r * XS_STRIDE;
        #pragma unroll
        for (int ii = 0; ii < 4; ii++) {
            float4 v = rx[ii];
            float4 o = make_float4(tf32f(v.x), tf32f(v.y), tf32f(v.z), tf32f(v.w));
            *(float4*)(row + (sub + 4 * ii) * 4) = o;
        }
        #pragma unroll
        for (int ii = 0; ii < 3; ii++) {
            float4 v = ra[ii];
            float4 o = make_float4(tf32f(v.x), tf32f(v.y), tf32f(v.z), tf32f(v.w));
            *(float4*)(row + 64 + (sub + 4 * ii) * 4) = o;
        }
        if (sub < 3) row[112 + sub] = tf32f(rc);
        if (sub == 0) {
            row[115] = 0.f;
            *(float4*)(row + 116) = make_float4(0.f, 0.f, 0.f, 0.f);
            sidx[r] = snode;
        }
    };

    int cur_typ = -1;
    stage_load(t_begin);

    for (int tile = t_begin; tile < t_end; tile++) {
        int typ = (tile < tiles0) ? 0 : 1;
        __syncthreads();   // prior MMA readers of xs/Ws done

        if (typ != cur_typ) {
            cur_typ = typ;
            const float* W1t = W1 + typ * (FIN * HH);
            const float* W2t = W2 + typ * (FIN * HH);
            for (int i = tid; i < 120 * 128; i += 512) {
                int kk = i >> 7, c = i & 127;
                float v = 0.f;
                if (kk < 64) v = (c < 64) ? W1t[kk * 64 + c] : W2t[kk * 64 + (c - 64)];
                else if (kk < 112) { if (c < 64) v = W5[(kk - 64) * 64 + c]; }
                else if (kk < 115) { if (c < 64) v = b5[(kk - 112) * 64 + c]; }
                Ws[kk * WS_STRIDE + c] = tf32f(v);
            }
            if (tid < 128)
                bc[tid] = (tid < 64) ? b1[typ * 64 + tid] : b2[typ * 64 + (tid - 64)];
        }

        stage_store();
        __syncthreads();

        if (tile + 1 < t_end) stage_load(tile + 1);   // LDGs overlap MMA below

        float acc[8][4];
        #pragma unroll
        for (int nt = 0; nt < 8; nt++)
            #pragma unroll
            for (int j = 0; j < 4; j++) acc[nt][j] = 0.f;

        #pragma unroll
        for (int kk = 0; kk < 120; kk += 8) {
            uint32_t a0 = __float_as_uint(xs[(rbase + g) * XS_STRIDE + kk + tq]);
            uint32_t a1 = __float_as_uint(xs[(rbase + g + 8) * XS_STRIDE + kk + tq]);
            uint32_t a2 = __float_as_uint(xs[(rbase + g) * XS_STRIDE + kk + tq + 4]);
            uint32_t a3 = __float_as_uint(xs[(rbase + g + 8) * XS_STRIDE + kk + tq + 4]);
            #pragma unroll
            for (int nt = 0; nt < 8; nt++) {
                int col0 = cbase + nt * 8;
                uint32_t b0 = __float_as_uint(Ws[(kk + tq) * WS_STRIDE + col0 + g]);
                uint32_t b1r = __float_as_uint(Ws[(kk + tq + 4) * WS_STRIDE + col0 + g]);
                mma_tf32(acc[nt], a0, a1, a2, a3, b0, b1r);
            }
        }

        __half2* h2p = (__half2*)g_h2h;
        float2* outp = (float2*)out;
        #pragma unroll
        for (int nt = 0; nt < 8; nt++) {
            int col0 = cbase + nt * 8 + 2 * tq;
            float bcv0 = bc[col0], bcv1 = bc[col0 + 1];
            #pragma unroll
            for (int half_r = 0; half_r < 2; half_r++) {
                int rr = rbase + g + half_r * 8;
                int node = sidx[rr];
                if (node < 0) continue;
                float v0 = acc[nt][half_r * 2 + 0] + bcv0;
                float v1 = acc[nt][half_r * 2 + 1] + bcv1;
                if (col0 < 64) {
                    outp[node * 32 + (col0 >> 1)] = make_float2(v0, v1);
                } else {
                    h2p[node * 32 + ((col0 - 64) >> 1)] = __floats2half2_rn(v0, v1);
                }
            }
        }
    }
}

// Bucket gather: out[dst] += sum_{incident} h2[src]; 16 lanes per node
__global__ __launch_bounds__(256)
void h2_gather_kernel(float* __restrict__ out) {
    int tid = threadIdx.x;
    int node = blockIdx.x * 16 + (tid >> 4);
    int q = tid & 15;
    if (node >= Nn) return;
    int deg = g_cur[node];
    if (deg > CAP) deg = CAP;
    if (deg == 0) return;

    const uint2* H = (const uint2*)g_h2h;
    const int* sl = &g_slots[(size_t)node * CAP];
    float4 acc = make_float4(0.f, 0.f, 0.f, 0.f);

    auto add4 = [&](uint2 hv) {
        float2 f0 = __half22float2(*(__half2*)&hv.x);
        float2 f1 = __half22float2(*(__half2*)&hv.y);
        acc.x += f0.x; acc.y += f0.y; acc.z += f1.x; acc.w += f1.y;
    };

    int i = 0;
    for (; i + 4 <= deg; i += 4) {
        int s0 = __ldg(&sl[i]);
        int s1 = __ldg(&sl[i + 1]);
        int s2 = __ldg(&sl[i + 2]);
        int s3 = __ldg(&sl[i + 3]);
        uint2 v0 = __ldg(&H[s0 * 16 + q]);
        uint2 v1 = __ldg(&H[s1 * 16 + q]);
        uint2 v2 = __ldg(&H[s2 * 16 + q]);
        uint2 v3 = __ldg(&H[s3 * 16 + q]);
        add4(v0); add4(v1); add4(v2); add4(v3);
    }
    for (; i < deg; i++) add4(__ldg(&H[__ldg(&sl[i]) * 16 + q]));

    float4* o4 = (float4*)out;
    float4 o = o4[node * 16 + q];
    o.x += acc.x; o.y += acc.y; o.z += acc.z; o.w += acc.w;
    o4[node * 16 + q] = o;
}

// Rare overflow edges (deg > CAP): atomic scatter
__global__ void ovf_kernel(float4* __restrict__ out) {
    int n = g_ovf_cnt;
    if (n > 8192) n = 8192;
    int stride = gridDim.x * blockDim.x;
    for (int i = blockIdx.x * blockDim.x + threadIdx.x; i < n * 16; i += stride) {
        int e = i >> 4, q = i & 15;
        int2 sd = g_ovf[e];
        uint2 hv = ((const uint2*)g_h2h)[sd.x * 16 + q];
        float2 f0 = __half22float2(*(__half2*)&hv.x);
        float2 f1 = __half22float2(*(__half2*)&hv.y);
        red_add_f4(&out[sd.y * 16 + q], make_float4(f0.x, f0.y, f1.x, f1.y));
    }
}

// ---------------- launch ----------------
extern "C" void kernel_launch(void* const* d_in, const int* in_sizes, int n_in,
                              void* d_out, int out_size) {
    const float *x = nullptr, *ef = nullptr;
    const float *W[4] = {nullptr, nullptr, nullptr, nullptr};
    const float *B[4] = {nullptr, nullptr, nullptr, nullptr};
    const float *W5 = nullptr, *b5 = nullptr;
    const int *ntype = nullptr, *esrc = nullptr, *edst = nullptr, *etype = nullptr;
    int wI = 0, bI = 0, mI = 0;
    for (int i = 0; i < n_in; i++) {
        long s = in_sizes[i];
        const void* p = d_in[i];
        if (s == (long)Nn * FIN)      x = (const float*)p;
        else if (s == (long)Mm * FE)  ef = (const float*)p;
        else if (s == Nn)             ntype = (const int*)p;
        else if (s == Mm) {
            if (mI == 0) esrc = (const int*)p;
            else if (mI == 1) edst = (const int*)p;
            else etype = (const int*)p;
            mI++;
        }
        else if (s == 2 * FIN * HH) { if (wI < 4) W[wI++] = (const float*)p; }
        else if (s == 2 * HH)       { if (bI < 4) B[bI++] = (const float*)p; }
        else if (s == 3 * FE * HH)  W5 = (const float*)p;
        else if (s == 3 * HH)       b5 = (const float*)p;
    }
    float* out = (float*)d_out;

    const int smem_bytes = (120 * WS_STRIDE + 128 * XS_STRIDE + 128) * 4 + 128 * 4;
    cudaFuncSetAttribute(node_gemm_kernel,
                         cudaFuncAttributeMaxDynamicSharedMemorySize, 160 * 1024);

    zero_kernel<<<2048, 256>>>();
    edge_scatter_kernel<<<(Mm * 4 + 255) / 256, 256>>>(ef, esrc, edst, etype);
    partition_kernel<<<(Nn + 255) / 256, 256>>>(ntype);
    node_gemm_kernel<<<148, 512, smem_bytes>>>(
        x, W[0], B[0], W[1], B[1], W5, b5, out);
    h2_gather_kernel<<<(Nn + 15) / 16, 256>>>(out);
    ovf_kernel<<<16, 256>>>((float4*)out);
}

// round 5
// speedup vs baseline: 2.3912x; 1.1514x over previous
#include <cuda_runtime.h>
#include <cuda_fp16.h>
#include <cstdint>

#define Nn 100000
#define Mm 800000
#define FIN 64
#define FE  16
#define HH  64
#define CAP 48

// ---------------- device scratch (no allocations allowed) ----------------
__device__ __half  g_h2h[(size_t)Nn * 64];    // h2 rows fp16 (128B/row)
__device__ float4  g_aggE[Nn * 12];           // aggregated edge_feat [N][3][16]
__device__ float   g_cntE[Nn * 3];            // per (dst, etype) counts
__device__ int     g_cur[Nn];                 // bucket cursors
__device__ int     g_slots[(size_t)Nn * CAP]; // bucket payload: src per incident edge
__device__ int     g_idx[2][Nn];              // per-type node lists
__device__ int     g_tcnt[2];
__device__ int     g_ovf_cnt;
__device__ int2    g_ovf[8192];               // overflow edges (src,dst)

__device__ __forceinline__ void red_add_f4(float4* p, float4 v) {
    asm volatile("red.global.add.v4.f32 [%0], {%1,%2,%3,%4};"
                 :: "l"(p), "f"(v.x), "f"(v.y), "f"(v.z), "f"(v.w)
                 : "memory");
}

__device__ __forceinline__ void mma_f16(float c[4], uint32_t a0, uint32_t a1,
                                        uint32_t a2, uint32_t a3,
                                        uint32_t b0, uint32_t b1) {
    asm volatile(
        "mma.sync.aligned.m16n8k16.row.col.f32.f16.f16.f32 "
        "{%0,%1,%2,%3},{%4,%5,%6,%7},{%8,%9},{%0,%1,%2,%3};"
        : "+f"(c[0]), "+f"(c[1]), "+f"(c[2]), "+f"(c[3])
        : "r"(a0), "r"(a1), "r"(a2), "r"(a3), "r"(b0), "r"(b1));
}

__device__ __forceinline__ uint32_t pack_h2(float a, float b) {
    __half2 h = __floats2half2_rn(a, b);
    return *(uint32_t*)&h;
}

// ---------------- kernels ----------------

__global__ void zero_kernel() {
    int gid = blockIdx.x * blockDim.x + threadIdx.x;
    int stride = gridDim.x * blockDim.x;
    float4 z = make_float4(0.f, 0.f, 0.f, 0.f);
    for (int i = gid; i < Nn * 12; i += stride) g_aggE[i] = z;
    for (int i = gid; i < Nn * 3; i += stride) g_cntE[i] = 0.f;
    for (int i = gid; i < Nn; i += stride) g_cur[i] = 0;
    if (gid < 2) g_tcnt[gid] = 0;
    if (gid == 2) g_ovf_cnt = 0;
}

// 4 threads/edge: scatter-add ef into aggE[dst][etype]; fused count + bucket fill
__global__ void edge_scatter_kernel(const float* __restrict__ ef,
                                    const int* __restrict__ esrc,
                                    const int* __restrict__ edst,
                                    const int* __restrict__ etype) {
    int gid = blockIdx.x * blockDim.x + threadIdx.x;
    int e = gid >> 2, q = gid & 3;
    if (e >= Mm) return;
    int dst = edst[e];
    int t   = etype[e];
    float4 v = ((const float4*)ef)[e * 4 + q];
    red_add_f4(&g_aggE[dst * 12 + t * 4 + q], v);
    if (q == 0) {
        atomicAdd(&g_cntE[dst * 3 + t], 1.0f);
        int src = esrc[e];
        int p = atomicAdd(&g_cur[dst], 1);
        if (p < CAP) {
            g_slots[(size_t)dst * CAP + p] = src;
        } else {
            int o = atomicAdd(&g_ovf_cnt, 1);
            if (o < 8192) g_ovf[o] = make_int2(src, dst);
        }
    }
}

// warp-aggregated partition by node type (2 atomics per warp)
__global__ void partition_kernel(const int* __restrict__ ntype) {
    const unsigned FULL = 0xffffffffu;
    int i = blockIdx.x * blockDim.x + threadIdx.x;
    int lane = threadIdx.x & 31;
    bool valid = (i < Nn);
    int t = valid ? ntype[i] : -1;
    unsigned m0 = __ballot_sync(FULL, t == 0);
    unsigned m1 = __ballot_sync(FULL, t == 1);
    int base0 = 0, base1 = 0;
    if (lane == 0) {
        if (m0) base0 = atomicAdd(&g_tcnt[0], __popc(m0));
        if (m1) base1 = atomicAdd(&g_tcnt[1], __popc(m1));
    }
    base0 = __shfl_sync(FULL, base0, 0);
    base1 = __shfl_sync(FULL, base1, 0);
    unsigned lt = (1u << lane) - 1u;
    if (t == 0) g_idx[0][base0 + __popc(m0 & lt)] = i;
    else if (t == 1) g_idx[1][base1 + __popc(m1 & lt)] = i;
}

// Persistent node GEMM (fp16 m16n8k16), 512 threads, tile M=128, reg-pipelined.
// Logical A[128 x 128] = [x(64) | aggE(48) | cnt(3) | 0(13)], fp16 packed as
// half2 along k (xs2[row][k2], k2=0..63, stride 68 words, bank-clean).
// B[128 x 128] = [[W1|W2],[W5|0],[b5|0],[0|0]] per type, packed Ws2[k2][n],
// stride 136 words (bank-clean).
// Output cols 0..63 -> out (fp32, h1+agg+b1); cols 64..127 -> g_h2h (fp16).
#define XSTR 68
#define WSTR 136
__global__ __launch_bounds__(512, 1)
void node_gemm_kernel(const float* __restrict__ x,
                      const float* __restrict__ W1, const float* __restrict__ b1,
                      const float* __restrict__ W2, const float* __restrict__ b2,
                      const float* __restrict__ W5, const float* __restrict__ b5,
                      float* __restrict__ out) {
    extern __shared__ uint32_t smu[];
    uint32_t* Ws2 = smu;                    // [64][136] half2 words
    uint32_t* xs2 = Ws2 + 64 * WSTR;        // [128][68] half2 words
    float* bc = (float*)(xs2 + 128 * XSTR); // [128]
    int* sidx = (int*)(bc + 128);           // [128]

    const int tid = threadIdx.x;
    const int w = tid >> 5, lane = tid & 31;
    const int g = lane >> 2, tq = lane & 3;
    const int rbase = (w & 7) * 16, cbase = (w >> 3) * 64;
    const int r = tid >> 2, sub = tid & 3;

    const int c0n = g_tcnt[0];
    const int tiles0 = (c0n + 127) >> 7;
    const int c1n = Nn - c0n;
    const int tiles1 = (c1n + 127) >> 7;
    const int total = tiles0 + tiles1;
    const int tpb = (total + gridDim.x - 1) / gridDim.x;
    const int t_begin = blockIdx.x * tpb;
    const int t_end = min(t_begin + tpb, total);
    if (t_begin >= t_end) return;

    // zero A tile once (pad regions k2 58..67 stay zero forever)
    for (int i = tid; i < 128 * XSTR; i += 512) xs2[i] = 0;

    // register staging (half2-packed at load time)
    uint2 hx[4], ha[3];
    uint32_t hcnt01 = 0;  // half2(cnt0, cnt1)
    uint32_t hcnt2 = 0;   // half2(cnt2, 0)
    int snode = -1;

    auto stage_load = [&](int tile) {
        int typ = (tile < tiles0) ? 0 : 1;
        const int* list = g_idx[typ];
        int base = ((typ == 0) ? tile : (tile - tiles0)) << 7;
        int cnt = (typ == 0) ? c0n : c1n;
        int j = base + r;
        snode = (j < cnt) ? list[j] : -1;
        if (snode >= 0) {
            const float4* x4 = (const float4*)x;
            #pragma unroll
            for (int ii = 0; ii < 4; ii++) {
                float4 v = x4[snode * 16 + sub + 4 * ii];
                hx[ii] = make_uint2(pack_h2(v.x, v.y), pack_h2(v.z, v.w));
            }
            #pragma unroll
            for (int ii = 0; ii < 3; ii++) {
                float4 v = g_aggE[snode * 12 + sub + 4 * ii];
                ha[ii] = make_uint2(pack_h2(v.x, v.y), pack_h2(v.z, v.w));
            }
            if (sub == 0) {
                float c0 = g_cntE[snode * 3 + 0];
                float c1 = g_cntE[snode * 3 + 1];
                float c2 = g_cntE[snode * 3 + 2];
                hcnt01 = pack_h2(c0, c1);
                hcnt2 = pack_h2(c2, 0.f);
            }
        } else {
            uint2 z = make_uint2(0u, 0u);
            #pragma unroll
            for (int ii = 0; ii < 4; ii++) hx[ii] = z;
            #pragma unroll
            for (int ii = 0; ii < 3; ii++) ha[ii] = z;
            hcnt01 = 0; hcnt2 = 0;
        }
    };

    auto stage_store = [&]() {
        uint32_t* row = xs2 + r * XSTR;
        #pragma unroll
        for (int ii = 0; ii < 4; ii++)
            *(uint2*)(row + 8 * ii + 2 * sub) = hx[ii];   // k2 = 8ii+2sub, +1
        #pragma unroll
        for (int ii = 0; ii < 3; ii++)
            *(uint2*)(row + 32 + 8 * ii + 2 * sub) = ha[ii];
        if (sub == 0) {
            row[56] = hcnt01;    // k 112,113
            row[57] = hcnt2;     // k 114, pad 0
            sidx[r] = snode;
        }
    };

    int cur_typ = -1;
    stage_load(t_begin);

    for (int tile = t_begin; tile < t_end; tile++) {
        int typ = (tile < tiles0) ? 0 : 1;
        __syncthreads();   // prior tile's readers done / zero-init done

        if (typ != cur_typ) {
            cur_typ = typ;
            const float* W1t = W1 + typ * (FIN * HH);
            const float* W2t = W2 + typ * (FIN * HH);
            for (int i = tid; i < 64 * 128; i += 512) {
                int k2 = i >> 7, c = i & 127;
                float v0, v1;
                // source value at (k, c) for k = 2*k2 and 2*k2+1
                #pragma unroll
                for (int h = 0; h < 2; h++) {
                    int kk = 2 * k2 + h;
                    float v = 0.f;
                    if (kk < 64) v = (c < 64) ? W1t[kk * 64 + c] : W2t[kk * 64 + (c - 64)];
                    else if (kk < 112) { if (c < 64) v = W5[(kk - 64) * 64 + c]; }
                    else if (kk < 115) { if (c < 64) v = b5[(kk - 112) * 64 + c]; }
                    if (h == 0) v0 = v; else v1 = v;
                }
                Ws2[k2 * WSTR + c] = pack_h2(v0, v1);
            }
            if (tid < 128)
                bc[tid] = (tid < 64) ? b1[typ * 64 + tid] : b2[typ * 64 + (tid - 64)];
        }

        stage_store();
        __syncthreads();

        if (tile + 1 < t_end) stage_load(tile + 1);   // LDGs overlap MMA below

        float acc[8][4];
        #pragma unroll
        for (int nt = 0; nt < 8; nt++)
            #pragma unroll
            for (int j = 0; j < 4; j++) acc[nt][j] = 0.f;

        #pragma unroll
        for (int kb = 0; kb < 8; kb++) {
            int kb2 = kb * 8;
            uint32_t a0 = xs2[(rbase + g) * XSTR + kb2 + tq];
            uint32_t a1 = xs2[(rbase + g + 8) * XSTR + kb2 + tq];
            uint32_t a2 = xs2[(rbase + g) * XSTR + kb2 + tq + 4];
            uint32_t a3 = xs2[(rbase + g + 8) * XSTR + kb2 + tq + 4];
            #pragma unroll
            for (int nt = 0; nt < 8; nt++) {
                int col0 = cbase + nt * 8;
                uint32_t b0 = Ws2[(kb2 + tq) * WSTR + col0 + g];
                uint32_t b1r = Ws2[(kb2 + tq + 4) * WSTR + col0 + g];
                mma_f16(acc[nt], a0, a1, a2, a3, b0, b1r);
            }
        }

        __half2* h2p = (__half2*)g_h2h;
        float2* outp = (float2*)out;
        #pragma unroll
        for (int nt = 0; nt < 8; nt++) {
            int col0 = cbase + nt * 8 + 2 * tq;
            float bcv0 = bc[col0], bcv1 = bc[col0 + 1];
            #pragma unroll
            for (int half_r = 0; half_r < 2; half_r++) {
                int rr = rbase + g + half_r * 8;
                int node = sidx[rr];
                if (node < 0) continue;
                float v0 = acc[nt][half_r * 2 + 0] + bcv0;
                float v1 = acc[nt][half_r * 2 + 1] + bcv1;
                if (col0 < 64) {
                    outp[node * 32 + (col0 >> 1)] = make_float2(v0, v1);
                } else {
                    h2p[node * 32 + ((col0 - 64) >> 1)] = __floats2half2_rn(v0, v1);
                }
            }
        }
    }
}

// Bucket gather: out[dst] += sum_{incident} h2[src]; 16 lanes per node
__global__ __launch_bounds__(256)
void h2_gather_kernel(float* __restrict__ out) {
    int tid = threadIdx.x;
    int node = blockIdx.x * 16 + (tid >> 4);
    int q = tid & 15;
    if (node >= Nn) return;
    int deg = g_cur[node];
    if (deg > CAP) deg = CAP;
    if (deg == 0) return;

    const uint2* H = (const uint2*)g_h2h;
    const int* sl = &g_slots[(size_t)node * CAP];
    float4 acc = make_float4(0.f, 0.f, 0.f, 0.f);

    auto add4 = [&](uint2 hv) {
        float2 f0 = __half22float2(*(__half2*)&hv.x);
        float2 f1 = __half22float2(*(__half2*)&hv.y);
        acc.x += f0.x; acc.y += f0.y; acc.z += f1.x; acc.w += f1.y;
    };

    int i = 0;
    for (; i + 4 <= deg; i += 4) {
        int s0 = __ldg(&sl[i]);
        int s1 = __ldg(&sl[i + 1]);
        int s2 = __ldg(&sl[i + 2]);
        int s3 = __ldg(&sl[i + 3]);
        uint2 v0 = __ldg(&H[s0 * 16 + q]);
        uint2 v1 = __ldg(&H[s1 * 16 + q]);
        uint2 v2 = __ldg(&H[s2 * 16 + q]);
        uint2 v3 = __ldg(&H[s3 * 16 + q]);
        add4(v0); add4(v1); add4(v2); add4(v3);
    }
    for (; i < deg; i++) add4(__ldg(&H[__ldg(&sl[i]) * 16 + q]));

    float4* o4 = (float4*)out;
    float4 o = o4[node * 16 + q];
    o.x += acc.x; o.y += acc.y; o.z += acc.z; o.w += acc.w;
    o4[node * 16 + q] = o;
}

// Rare overflow edges (deg > CAP): atomic scatter
__global__ void ovf_kernel(float4* __restrict__ out) {
    int n = g_ovf_cnt;
    if (n > 8192) n = 8192;
    int stride = gridDim.x * blockDim.x;
    for (int i = blockIdx.x * blockDim.x + threadIdx.x; i < n * 16; i += stride) {
        int e = i >> 4, q = i & 15;
        int2 sd = g_ovf[e];
        uint2 hv = ((const uint2*)g_h2h)[sd.x * 16 + q];
        float2 f0 = __half22float2(*(__half2*)&hv.x);
        float2 f1 = __half22float2(*(__half2*)&hv.y);
        red_add_f4(&out[sd.y * 16 + q], make_float4(f0.x, f0.y, f1.x, f1.y));
    }
}

// ---------------- launch ----------------
extern "C" void kernel_launch(void* const* d_in, const int* in_sizes, int n_in,
                              void* d_out, int out_size) {
    const float *x = nullptr, *ef = nullptr;
    const float *W[4] = {nullptr, nullptr, nullptr, nullptr};
    const float *B[4] = {nullptr, nullptr, nullptr, nullptr};
    const float *W5 = nullptr, *b5 = nullptr;
    const int *ntype = nullptr, *esrc = nullptr, *edst = nullptr, *etype = nullptr;
    int wI = 0, bI = 0, mI = 0;
    for (int i = 0; i < n_in; i++) {
        long s = in_sizes[i];
        const void* p = d_in[i];
        if (s == (long)Nn * FIN)      x = (const float*)p;
        else if (s == (long)Mm * FE)  ef = (const float*)p;
        else if (s == Nn)             ntype = (const int*)p;
        else if (s == Mm) {
            if (mI == 0) esrc = (const int*)p;
            else if (mI == 1) edst = (const int*)p;
            else etype = (const int*)p;
            mI++;
        }
        else if (s == 2 * FIN * HH) { if (wI < 4) W[wI++] = (const float*)p; }
        else if (s == 2 * HH)       { if (bI < 4) B[bI++] = (const float*)p; }
        else if (s == 3 * FE * HH)  W5 = (const float*)p;
        else if (s == 3 * HH)       b5 = (const float*)p;
    }
    float* out = (float*)d_out;

    const int smem_bytes = (64 * WSTR + 128 * XSTR + 128 + 128) * 4;
    cudaFuncSetAttribute(node_gemm_kernel,
                         cudaFuncAttributeMaxDynamicSharedMemorySize, 100 * 1024);

    zero_kernel<<<2048, 256>>>();
    edge_scatter_kernel<<<(Mm * 4 + 255) / 256, 256>>>(ef, esrc, edst, etype);
    partition_kernel<<<(Nn + 255) / 256, 256>>>(ntype);
    node_gemm_kernel<<<148, 512, smem_bytes>>>(
        x, W[0], B[0], W[1], B[1], W5, b5, out);
    h2_gather_kernel<<<(Nn + 15) / 16, 256>>>(out);
    ovf_kernel<<<16, 256>>>((float4*)out);
}